// round 6
// baseline (speedup 1.0000x reference)
#include <cuda_runtime.h>

#define NBATCH 4
#define HH 128
#define WW 128
#define TT 32

typedef unsigned long long ull;

// ---------------- f32x2 packed-math helpers (sm_103a) -----------------------
__device__ __forceinline__ ull f2fma(ull a, ull b, ull c) {
    ull d;
    asm("fma.rn.f32x2 %0, %1, %2, %3;" : "=l"(d) : "l"(a), "l"(b), "l"(c));
    return d;
}
__device__ __forceinline__ ull f2pack(float lo, float hi) {
    ull r; asm("mov.b64 %0, {%1, %2};" : "=l"(r) : "f"(lo), "f"(hi)); return r;
}
__device__ __forceinline__ void f2unpack(ull v, float& lo, float& hi) {
    asm("mov.b64 {%0, %1}, %2;" : "=f"(lo), "=f"(hi) : "l"(v));
}

// ---------------- tables + scratch (device globals: no runtime allocation) ----
static __device__ float g_srm0[32];
static __device__ float g_refc1[32];
static __device__ float g_refc2[32];

static __device__ float g_psp0 [(size_t)NBATCH * 2  * HH * WW * TT]; //  16 MB
static __device__ float g_psps1[(size_t)NBATCH * 16 * HH * WW * TT]; // 128 MB
static __device__ float g_p2   [(size_t)NBATCH * 16 * HH * WW * TT]; // 128 MB

#define Q1F  0.60653065971263342f  /* exp(-1/2)  */
#define Q2F  0.77880078307140487f  /* exp(-1/4)  */
#define CS1F 1.3591409142295226f   /* e/2 : srm1[k] = CS1*k*Q1^k */
#define CS2F 0.67957045711476131f  /* e/4 : srm2[k] = CS2*k*Q2^k */

// ---------------- init: alpha-kernel tables (match reference truncation) -----
__global__ void k_init() {
    int t = threadIdx.x;
    if (t < 32) {
        double td = (double)t;
        double v0 = td * exp(1.0 - td);                      // srm0 (tau=1), trunc@18
        g_srm0[t]  = (t < 18) ? (float)v0 : 0.0f;
        double r1 = -3.0 * td * exp(1.0 - td);               // refk layer1, trunc@19
        g_refc1[t] = (t < 19) ? (float)r1 : 0.0f;
        double r2 = -5.0 * (td * 0.5) * exp(1.0 - td * 0.5); // refk layer2, full 32
        g_refc2[t] = (float)r2;
    }
}

// ---------------- psp0: temporal filter of binary input ---------------------
__global__ void __launch_bounds__(256) k_psp0(const float* __restrict__ in) {
    int gid = blockIdx.x * blockDim.x + threadIdx.x;   // (n,c,h,w) : 131072
    const float4* src = (const float4*)(in + (size_t)gid * TT);
    float x[TT];
#pragma unroll
    for (int v = 0; v < 8; v++) {
        float4 f = src[v];
        x[4*v] = f.x; x[4*v+1] = f.y; x[4*v+2] = f.z; x[4*v+3] = f.w;
    }
    float s0[18];
#pragma unroll
    for (int k = 0; k < 18; k++) s0[k] = g_srm0[k];
    float y[TT];
#pragma unroll
    for (int t = 0; t < TT; t++) {
        float a = 0.f;
#pragma unroll
        for (int k = 1; k < 18; k++)
            if (k <= t) a += x[t - k] * s0[k];
        y[t] = a;
    }
    float4* dst = (float4*)(g_psp0 + (size_t)gid * TT);
#pragma unroll
    for (int v = 0; v < 8; v++)
        dst[v] = make_float4(y[4*v], y[4*v+1], y[4*v+2], y[4*v+3]);
}

// ---------------- fused: conv1 (3x3, 2->16) + spike1 + psp(s1,srm1) ---------
// smem-tiled: block = 16x16 pixels; per-thread loop over 16 co.
// tile row stride 36 floats (144B) -> conflict-free LDS.128 across x-lanes.
#define L1_RS 36
__global__ void __launch_bounds__(256) k_l1(const float* __restrict__ w1) {
    extern __shared__ float tile[];      // [2][18][18][L1_RS]  (ci, yy, xx, t)
    __shared__ float wL[288];

    int tid = threadIdx.x;
    int w0 = blockIdx.x * 16, h0 = blockIdx.y * 16;
    int n  = blockIdx.z;

    for (int i = tid; i < 288; i += 256) wL[i] = w1[i];
    for (int i = tid; i < 5184; i += 256) {      // 2*18*18*8 float4 chunks
        int ci  = i / 2592;
        int rem = i - ci * 2592;
        int yy  = rem / 144;
        int r2  = rem - yy * 144;
        int xx  = r2 >> 3, v = r2 & 7;
        int gh = h0 + yy - 1, gw = w0 + xx - 1;
        float4 val = make_float4(0.f, 0.f, 0.f, 0.f);
        if ((unsigned)gh < 128u && (unsigned)gw < 128u)
            val = *(const float4*)(g_psp0 +
                ((((size_t)n * 2 + ci) * 128 + gh) * 128 + gw) * TT + v * 4);
        *(float4*)&tile[((ci * 18 + yy) * 18 + xx) * L1_RS + v * 4] = val;
    }
    __syncthreads();

    int x = tid & 15, y = tid >> 4;
    int gh = h0 + y, gw = w0 + x;

    float rc[19];
#pragma unroll
    for (int d = 1; d < 19; d++) rc[d] = g_refc1[d];

    for (int co = 0; co < 16; co++) {
        ull acc2[16];
#pragma unroll
        for (int i = 0; i < 16; i++) acc2[i] = 0ull;

#pragma unroll
        for (int ci = 0; ci < 2; ci++)
#pragma unroll
            for (int ky = 0; ky < 3; ky++)
#pragma unroll
                for (int kx = 0; kx < 3; kx++) {
                    float wgt = wL[co * 18 + ci * 9 + ky * 3 + kx];
                    ull wp = f2pack(wgt, wgt);
                    const ulonglong2* p = (const ulonglong2*)
                        &tile[((ci * 18 + (y + ky)) * 18 + (x + kx)) * L1_RS];
#pragma unroll
                    for (int v = 0; v < 8; v++) {
                        ulonglong2 f = p[v];
                        acc2[2*v]   = f2fma(f.x, wp, acc2[2*v]);
                        acc2[2*v+1] = f2fma(f.y, wp, acc2[2*v+1]);
                    }
                }

        float acc[TT];
#pragma unroll
        for (int v = 0; v < 16; v++) f2unpack(acc2[v], acc[2*v], acc[2*v+1]);

        // spike1 (theta=3, refractory len 19, exact replay) + psp1 recurrence
        float r[TT];
#pragma unroll
        for (int t = 0; t < TT; t++) r[t] = 0.f;
        float A = 0.f, B = 0.f;
#pragma unroll
        for (int t = 0; t < TT; t++) {
            float u = acc[t] + r[t];
            bool sp = (u >= 3.0f);
            B = Q1F * (B + A);
            A = Q1F * A + (sp ? 1.0f : 0.0f);
            acc[t] = CS1F * B;             // psp(s1)
            if (sp) {
#pragma unroll
                for (int d = 1; d < 19; d++)
                    if (t + d < TT) r[t + d] += rc[d];
            }
        }

        float4* dst = (float4*)(g_psps1 +
            ((((size_t)n * 16 + co) * 128 + gh) * 128 + gw) * TT);
#pragma unroll
        for (int v = 0; v < 8; v++)
            dst[v] = make_float4(acc[4*v], acc[4*v+1], acc[4*v+2], acc[4*v+3]);
    }
}

// ---------------- conv2 (3x3, 18->16), smem tiled, co-pair packed f32x2 -----
// block = 16x16 pixels, one (n, t-chunk of 4); thread = 1 pixel x 16co x 4t
// acc2[cp*4+t] holds (co=2cp, co=2cp+1) at time t0+t.
__global__ void __launch_bounds__(256, 2) k_conv2(const float* __restrict__ w2) {
    extern __shared__ float smem[];
    float* tile = smem;                       // [18][18][18][4]  (ci, yy, xx, tt)
    ull*   wP   = (ull*)(smem + 23328);       // [162 taps][8 co-pairs]

    int tid = threadIdx.x;
    int x = tid & 15, y = tid >> 4;
    int w0 = blockIdx.x * 16, h0 = blockIdx.y * 16;
    int bz = blockIdx.z;
    int n = bz >> 3, t0 = (bz & 7) * 4;

    for (int i = tid; i < 1296; i += 256) {   // w2: [co][tap]
        int cp = i & 7, tap = i >> 3;
        wP[i] = f2pack(w2[(2*cp) * 162 + tap], w2[(2*cp+1) * 162 + tap]);
    }
    for (int i = tid; i < 5832; i += 256) {   // 18*18*18 float4 chunks
        int ci  = i / 324;
        int rem = i - ci * 324;
        int yy = rem / 18, xx = rem - yy * 18;
        int gh = h0 + yy - 1, gw = w0 + xx - 1;
        float4 v = make_float4(0.f, 0.f, 0.f, 0.f);
        if ((unsigned)gh < 128u && (unsigned)gw < 128u) {
            const float* srcp = (ci < 16)
                ? (g_psps1 + ((((size_t)n * 16 + ci)        * 128 + gh) * 128 + gw) * TT + t0)
                : (g_psp0  + ((((size_t)n * 2  + (ci - 16)) * 128 + gh) * 128 + gw) * TT + t0);
            v = *(const float4*)srcp;
        }
        *(float4*)&tile[(size_t)i * 4] = v;
    }
    __syncthreads();

    ull acc2[32];
#pragma unroll
    for (int i = 0; i < 32; i++) acc2[i] = 0ull;

    for (int ci = 0; ci < 18; ci++) {
#pragma unroll
        for (int ky = 0; ky < 3; ky++)
#pragma unroll
            for (int kx = 0; kx < 3; kx++) {
                float4 in4 = *(const float4*)
                    &tile[(((ci * 18) + (y + ky)) * 18 + (x + kx)) * 4];
                ull d0 = f2pack(in4.x, in4.x);
                ull d1 = f2pack(in4.y, in4.y);
                ull d2 = f2pack(in4.z, in4.z);
                ull d3 = f2pack(in4.w, in4.w);
                const ulonglong2* wrow = (const ulonglong2*)&wP[(ci * 9 + ky * 3 + kx) * 8];
                ulonglong2 wa = wrow[0], wb = wrow[1], wc = wrow[2], wd = wrow[3];
                acc2[ 0] = f2fma(d0, wa.x, acc2[ 0]);
                acc2[ 1] = f2fma(d1, wa.x, acc2[ 1]);
                acc2[ 2] = f2fma(d2, wa.x, acc2[ 2]);
                acc2[ 3] = f2fma(d3, wa.x, acc2[ 3]);
                acc2[ 4] = f2fma(d0, wa.y, acc2[ 4]);
                acc2[ 5] = f2fma(d1, wa.y, acc2[ 5]);
                acc2[ 6] = f2fma(d2, wa.y, acc2[ 6]);
                acc2[ 7] = f2fma(d3, wa.y, acc2[ 7]);
                acc2[ 8] = f2fma(d0, wb.x, acc2[ 8]);
                acc2[ 9] = f2fma(d1, wb.x, acc2[ 9]);
                acc2[10] = f2fma(d2, wb.x, acc2[10]);
                acc2[11] = f2fma(d3, wb.x, acc2[11]);
                acc2[12] = f2fma(d0, wb.y, acc2[12]);
                acc2[13] = f2fma(d1, wb.y, acc2[13]);
                acc2[14] = f2fma(d2, wb.y, acc2[14]);
                acc2[15] = f2fma(d3, wb.y, acc2[15]);
                acc2[16] = f2fma(d0, wc.x, acc2[16]);
                acc2[17] = f2fma(d1, wc.x, acc2[17]);
                acc2[18] = f2fma(d2, wc.x, acc2[18]);
                acc2[19] = f2fma(d3, wc.x, acc2[19]);
                acc2[20] = f2fma(d0, wc.y, acc2[20]);
                acc2[21] = f2fma(d1, wc.y, acc2[21]);
                acc2[22] = f2fma(d2, wc.y, acc2[22]);
                acc2[23] = f2fma(d3, wc.y, acc2[23]);
                acc2[24] = f2fma(d0, wd.x, acc2[24]);
                acc2[25] = f2fma(d1, wd.x, acc2[25]);
                acc2[26] = f2fma(d2, wd.x, acc2[26]);
                acc2[27] = f2fma(d3, wd.x, acc2[27]);
                acc2[28] = f2fma(d0, wd.y, acc2[28]);
                acc2[29] = f2fma(d1, wd.y, acc2[29]);
                acc2[30] = f2fma(d2, wd.y, acc2[30]);
                acc2[31] = f2fma(d3, wd.y, acc2[31]);
            }
    }

    int gh = h0 + y, gw = w0 + x;
#pragma unroll
    for (int cp = 0; cp < 8; cp++) {
        float e0,e1,e2,e3, o0,o1,o2,o3;
        f2unpack(acc2[cp*4+0], e0, o0);
        f2unpack(acc2[cp*4+1], e1, o1);
        f2unpack(acc2[cp*4+2], e2, o2);
        f2unpack(acc2[cp*4+3], e3, o3);
        size_t oe = ((((size_t)n * 16 + 2*cp    ) * 128 + gh) * 128 + gw) * TT + t0;
        size_t oo = ((((size_t)n * 16 + 2*cp + 1) * 128 + gh) * 128 + gw) * TT + t0;
        *(float4*)&g_p2[oe] = make_float4(e0, e1, e2, e3);
        *(float4*)&g_p2[oo] = make_float4(o0, o1, o2, o3);
    }
}

// ---------------- fused: spike2 (theta=5) + psp(s2,srm2) + conv3 (1x1) ------
#define SM_STRIDE 36
__global__ void __launch_bounds__(256, 2) k_l3(const float* __restrict__ w3,
                                               float* __restrict__ out) {
    __shared__ float sm_in[18 * 16 * SM_STRIDE];   // [ci][p][t], padded stride
    __shared__ ull   wS[18 * 16];                  // [ci][16 co-pairs]

    int tid = threadIdx.x;
    int n = blockIdx.z, h = blockIdx.y, w0 = blockIdx.x * 16;

    for (int i = tid; i < 288; i += 256) {         // w3: [co][ci]
        int cp = i & 15, ci = i >> 4;
        wS[i] = f2pack(w3[(2*cp) * 18 + ci], w3[(2*cp+1) * 18 + ci]);
    }

    // ---- phase 1: spike2 + psp(s2) per (pixel, channel) ----
    {
        int p  = tid & 15;
        int ci = tid >> 4;
        const float4* src = (const float4*)(g_p2 +
            ((((size_t)n * 16 + ci) * 128 + h) * 128 + (w0 + p)) * TT);
        float pv[TT];
#pragma unroll
        for (int v = 0; v < 8; v++) {
            float4 f = src[v];
            pv[4*v] = f.x; pv[4*v+1] = f.y; pv[4*v+2] = f.z; pv[4*v+3] = f.w;
        }
        float rc[32];
#pragma unroll
        for (int d = 1; d < 32; d++) rc[d] = g_refc2[d];
        float r[TT];
#pragma unroll
        for (int t = 0; t < TT; t++) r[t] = 0.f;
        float A = 0.f, B = 0.f;
#pragma unroll
        for (int t = 0; t < TT; t++) {
            float u = pv[t] + r[t];
            bool sp = (u >= 5.0f);
            B = Q2F * (B + A);
            A = Q2F * A + (sp ? 1.0f : 0.0f);
            pv[t] = CS2F * B;                  // psp(s2)
            if (sp) {
#pragma unroll
                for (int d = 1; d < 32; d++)
                    if (t + d < TT) r[t + d] += rc[d];
            }
        }
        float* drow = &sm_in[(ci * 16 + p) * SM_STRIDE];
#pragma unroll
        for (int v = 0; v < 8; v++)
            *(float4*)&drow[4*v] = make_float4(pv[4*v], pv[4*v+1], pv[4*v+2], pv[4*v+3]);

        if (tid < 32) {                        // psp0 channels 16,17
            int pp = tid & 15, c = tid >> 4;
            const float4* s2 = (const float4*)(g_psp0 +
                (((size_t)n * 2 + c) * 16384 + h * 128 + (w0 + pp)) * TT);
            float* dr = &sm_in[((16 + c) * 16 + pp) * SM_STRIDE];
#pragma unroll
            for (int v = 0; v < 8; v++) *(float4*)&dr[4*v] = s2[v];
        }
    }
    __syncthreads();

    // ---- phase 2: 1x1 conv (18 -> 32), co-pair packed f32x2 ----
    int p  = tid >> 4;
    int q  = tid & 15;
    int ch = q >> 3;               // co half (0: co 0-15, 1: co 16-31)
    int t0 = (q & 7) * 4;

    ull acc2[32];
#pragma unroll
    for (int i = 0; i < 32; i++) acc2[i] = 0ull;

#pragma unroll
    for (int ci = 0; ci < 18; ci++) {
        float4 in4 = *(const float4*)&sm_in[(ci * 16 + p) * SM_STRIDE + t0];
        ull d0 = f2pack(in4.x, in4.x);
        ull d1 = f2pack(in4.y, in4.y);
        ull d2 = f2pack(in4.z, in4.z);
        ull d3 = f2pack(in4.w, in4.w);
        const ulonglong2* wrow = (const ulonglong2*)&wS[ci * 16 + ch * 8];
        ulonglong2 wa = wrow[0], wb = wrow[1], wc = wrow[2], wd = wrow[3];
        acc2[ 0] = f2fma(d0, wa.x, acc2[ 0]);  acc2[ 1] = f2fma(d1, wa.x, acc2[ 1]);
        acc2[ 2] = f2fma(d2, wa.x, acc2[ 2]);  acc2[ 3] = f2fma(d3, wa.x, acc2[ 3]);
        acc2[ 4] = f2fma(d0, wa.y, acc2[ 4]);  acc2[ 5] = f2fma(d1, wa.y, acc2[ 5]);
        acc2[ 6] = f2fma(d2, wa.y, acc2[ 6]);  acc2[ 7] = f2fma(d3, wa.y, acc2[ 7]);
        acc2[ 8] = f2fma(d0, wb.x, acc2[ 8]);  acc2[ 9] = f2fma(d1, wb.x, acc2[ 9]);
        acc2[10] = f2fma(d2, wb.x, acc2[10]);  acc2[11] = f2fma(d3, wb.x, acc2[11]);
        acc2[12] = f2fma(d0, wb.y, acc2[12]);  acc2[13] = f2fma(d1, wb.y, acc2[13]);
        acc2[14] = f2fma(d2, wb.y, acc2[14]);  acc2[15] = f2fma(d3, wb.y, acc2[15]);
        acc2[16] = f2fma(d0, wc.x, acc2[16]);  acc2[17] = f2fma(d1, wc.x, acc2[17]);
        acc2[18] = f2fma(d2, wc.x, acc2[18]);  acc2[19] = f2fma(d3, wc.x, acc2[19]);
        acc2[20] = f2fma(d0, wc.y, acc2[20]);  acc2[21] = f2fma(d1, wc.y, acc2[21]);
        acc2[22] = f2fma(d2, wc.y, acc2[22]);  acc2[23] = f2fma(d3, wc.y, acc2[23]);
        acc2[24] = f2fma(d0, wd.x, acc2[24]);  acc2[25] = f2fma(d1, wd.x, acc2[25]);
        acc2[26] = f2fma(d2, wd.x, acc2[26]);  acc2[27] = f2fma(d3, wd.x, acc2[27]);
        acc2[28] = f2fma(d0, wd.y, acc2[28]);  acc2[29] = f2fma(d1, wd.y, acc2[29]);
        acc2[30] = f2fma(d2, wd.y, acc2[30]);  acc2[31] = f2fma(d3, wd.y, acc2[31]);
    }

    int hw = h * 128 + w0 + p;
#pragma unroll
    for (int cp = 0; cp < 8; cp++) {
        float e0,e1,e2,e3, o0,o1,o2,o3;
        f2unpack(acc2[cp*4+0], e0, o0);
        f2unpack(acc2[cp*4+1], e1, o1);
        f2unpack(acc2[cp*4+2], e2, o2);
        f2unpack(acc2[cp*4+3], e3, o3);
        int coe = ch * 16 + 2 * cp;
        size_t oe = (((size_t)n * 32 + coe    ) * 16384 + hw) * TT + t0;
        size_t oo = (((size_t)n * 32 + coe + 1) * 16384 + hw) * TT + t0;
        *(float4*)(out + oe) = make_float4(e0, e1, e2, e3);
        *(float4*)(out + oo) = make_float4(o0, o1, o2, o3);
    }
}

// ---------------- launcher ---------------------------------------------------
extern "C" void kernel_launch(void* const* d_in, const int* in_sizes, int n_in,
                              void* d_out, int out_size) {
    const float* spikeIn = (const float*)d_in[0];
    const float* w1 = (const float*)d_in[1];
    const float* w2 = (const float*)d_in[2];
    const float* w3 = (const float*)d_in[3];
    float* out = (float*)d_out;

    const int l1_smem    = 2 * 18 * 18 * L1_RS * 4;      // 93,312 B
    const int conv2_smem = 23328 * 4 + 1296 * 8;         // 103,680 B
    cudaFuncSetAttribute(k_l1,    cudaFuncAttributeMaxDynamicSharedMemorySize, l1_smem);
    cudaFuncSetAttribute(k_conv2, cudaFuncAttributeMaxDynamicSharedMemorySize, conv2_smem);

    k_init<<<1, 32>>>();
    k_psp0<<<512, 256>>>(spikeIn);
    dim3 g1(8, 8, 4);
    k_l1<<<g1, 256, l1_smem>>>(w1);
    dim3 g2(8, 8, 32);
    k_conv2<<<g2, 256, conv2_smem>>>(w2);
    dim3 g3(8, 128, 4);
    k_l3<<<g3, 256>>>(w3, out);
}

// round 7
// speedup vs baseline: 1.2416x; 1.2416x over previous
#include <cuda_runtime.h>

#define NBATCH 4
#define HH 128
#define WW 128
#define TT 32

typedef unsigned long long ull;

// ---------------- f32x2 packed-math helpers (sm_103a) -----------------------
__device__ __forceinline__ ull f2fma(ull a, ull b, ull c) {
    ull d;
    asm("fma.rn.f32x2 %0, %1, %2, %3;" : "=l"(d) : "l"(a), "l"(b), "l"(c));
    return d;
}
__device__ __forceinline__ ull f2pack(float lo, float hi) {
    ull r; asm("mov.b64 %0, {%1, %2};" : "=l"(r) : "f"(lo), "f"(hi)); return r;
}
__device__ __forceinline__ void f2unpack(ull v, float& lo, float& hi) {
    asm("mov.b64 {%0, %1}, %2;" : "=f"(lo), "=f"(hi) : "l"(v));
}

// ---------------- tables + scratch (device globals: no runtime allocation) ----
static __device__ float g_srm0[32];
static __device__ float g_refc1[32];
static __device__ float g_refc2[32];

static __device__ float g_psp0 [(size_t)NBATCH * 2  * HH * WW * TT]; //  16 MB
static __device__ float g_psps1[(size_t)NBATCH * 16 * HH * WW * TT]; // 128 MB
static __device__ float g_p2   [(size_t)NBATCH * 16 * HH * WW * TT]; // 128 MB

#define Q1F  0.60653065971263342f  /* exp(-1/2)  */
#define Q2F  0.77880078307140487f  /* exp(-1/4)  */
#define CS1F 1.3591409142295226f   /* e/2 : srm1[k] = CS1*k*Q1^k */
#define CS2F 0.67957045711476131f  /* e/4 : srm2[k] = CS2*k*Q2^k */

// ---------------- init: alpha-kernel tables (match reference truncation) -----
__global__ void k_init() {
    int t = threadIdx.x;
    if (t < 32) {
        double td = (double)t;
        double v0 = td * exp(1.0 - td);                      // srm0 (tau=1), trunc@18
        g_srm0[t]  = (t < 18) ? (float)v0 : 0.0f;
        double r1 = -3.0 * td * exp(1.0 - td);               // refk layer1, trunc@19
        g_refc1[t] = (t < 19) ? (float)r1 : 0.0f;
        double r2 = -5.0 * (td * 0.5) * exp(1.0 - td * 0.5); // refk layer2, full 32
        g_refc2[t] = (float)r2;
    }
}

// ---------------- psp0: temporal filter of binary input ---------------------
__global__ void __launch_bounds__(256) k_psp0(const float* __restrict__ in) {
    int gid = blockIdx.x * blockDim.x + threadIdx.x;   // (n,c,h,w) : 131072
    const float4* src = (const float4*)(in + (size_t)gid * TT);
    float x[TT];
#pragma unroll
    for (int v = 0; v < 8; v++) {
        float4 f = src[v];
        x[4*v] = f.x; x[4*v+1] = f.y; x[4*v+2] = f.z; x[4*v+3] = f.w;
    }
    float s0[18];
#pragma unroll
    for (int k = 0; k < 18; k++) s0[k] = g_srm0[k];
    float y[TT];
#pragma unroll
    for (int t = 0; t < TT; t++) {
        float a = 0.f;
#pragma unroll
        for (int k = 1; k < 18; k++)
            if (k <= t) a += x[t - k] * s0[k];
        y[t] = a;
    }
    float4* dst = (float4*)(g_psp0 + (size_t)gid * TT);
#pragma unroll
    for (int v = 0; v < 8; v++)
        dst[v] = make_float4(y[4*v], y[4*v+1], y[4*v+2], y[4*v+3]);
}

// ---------------- fused: conv1 (3x3, 2->16) + spike1 + psp(s1,srm1) ---------
// smem-tiled: block = 16x16 pixels; per-thread loop over 16 co.
// tile row stride 36 floats (144B) -> conflict-free LDS.128 across x-lanes.
#define L1_RS 36
__global__ void __launch_bounds__(256) k_l1(const float* __restrict__ w1) {
    extern __shared__ float tile[];      // [2][18][18][L1_RS]  (ci, yy, xx, t)
    __shared__ float wL[288];

    int tid = threadIdx.x;
    int w0 = blockIdx.x * 16, h0 = blockIdx.y * 16;
    int n  = blockIdx.z;

    for (int i = tid; i < 288; i += 256) wL[i] = w1[i];
    for (int i = tid; i < 5184; i += 256) {      // 2*18*18*8 float4 chunks
        int ci  = i / 2592;
        int rem = i - ci * 2592;
        int yy  = rem / 144;
        int r2  = rem - yy * 144;
        int xx  = r2 >> 3, v = r2 & 7;
        int gh = h0 + yy - 1, gw = w0 + xx - 1;
        float4 val = make_float4(0.f, 0.f, 0.f, 0.f);
        if ((unsigned)gh < 128u && (unsigned)gw < 128u)
            val = *(const float4*)(g_psp0 +
                ((((size_t)n * 2 + ci) * 128 + gh) * 128 + gw) * TT + v * 4);
        *(float4*)&tile[((ci * 18 + yy) * 18 + xx) * L1_RS + v * 4] = val;
    }
    __syncthreads();

    int x = tid & 15, y = tid >> 4;
    int gh = h0 + y, gw = w0 + x;

    float rc[19];
#pragma unroll
    for (int d = 1; d < 19; d++) rc[d] = g_refc1[d];

    for (int co = 0; co < 16; co++) {
        ull acc2[16];
#pragma unroll
        for (int i = 0; i < 16; i++) acc2[i] = 0ull;

#pragma unroll
        for (int ci = 0; ci < 2; ci++)
#pragma unroll
            for (int ky = 0; ky < 3; ky++)
#pragma unroll
                for (int kx = 0; kx < 3; kx++) {
                    float wgt = wL[co * 18 + ci * 9 + ky * 3 + kx];
                    ull wp = f2pack(wgt, wgt);
                    const ulonglong2* p = (const ulonglong2*)
                        &tile[((ci * 18 + (y + ky)) * 18 + (x + kx)) * L1_RS];
#pragma unroll
                    for (int v = 0; v < 8; v++) {
                        ulonglong2 f = p[v];
                        acc2[2*v]   = f2fma(f.x, wp, acc2[2*v]);
                        acc2[2*v+1] = f2fma(f.y, wp, acc2[2*v+1]);
                    }
                }

        float acc[TT];
#pragma unroll
        for (int v = 0; v < 16; v++) f2unpack(acc2[v], acc[2*v], acc[2*v+1]);

        // spike1 (theta=3, refractory len 19, exact replay) + psp1 recurrence
        float r[TT];
#pragma unroll
        for (int t = 0; t < TT; t++) r[t] = 0.f;
        float A = 0.f, B = 0.f;
#pragma unroll
        for (int t = 0; t < TT; t++) {
            float u = acc[t] + r[t];
            bool sp = (u >= 3.0f);
            B = Q1F * (B + A);
            A = Q1F * A + (sp ? 1.0f : 0.0f);
            acc[t] = CS1F * B;             // psp(s1)
            if (sp) {
#pragma unroll
                for (int d = 1; d < 19; d++)
                    if (t + d < TT) r[t + d] += rc[d];
            }
        }

        float4* dst = (float4*)(g_psps1 +
            ((((size_t)n * 16 + co) * 128 + gh) * 128 + gw) * TT);
#pragma unroll
        for (int v = 0; v < 8; v++)
            dst[v] = make_float4(acc[4*v], acc[4*v+1], acc[4*v+2], acc[4*v+3]);
    }
}

// ---------------- conv2 (3x3, 18->16), smem tiled, f32x2, 2-pixel threads ---
// block = 16x16 pixel tile, one (n, t-chunk of 4).
// thread = 2 pixels (x, x+8) x 8 co x 4 t. warps 0-3: co 0-7; warps 4-7: co 8-15.
// Per tap: 2 input LDS.128 + 4 weight LDS.128 for 32 FFMA2 (R5 was 9 LDS / 32).
__global__ void __launch_bounds__(256, 2) k_conv2(const float* __restrict__ w2) {
    extern __shared__ float smem[];
    float* tile = smem;                       // [18][18][18][4]  (ci, yy, xx, tt)
    ull*   wP   = (ull*)(smem + 23328);       // [162 taps][16 co] (w,w) pairs

    int tid = threadIdx.x;
    int cg = tid >> 7;                        // co-group: 0 -> co 0-7, 1 -> co 8-15
    int p  = tid & 127;
    int x = p & 7, y = p >> 3;                // pixel pair (y, x) and (y, x+8)
    int w0 = blockIdx.x * 16, h0 = blockIdx.y * 16;
    int bz = blockIdx.z;
    int n = bz >> 3, t0 = (bz & 7) * 4;

    for (int i = tid; i < 2592; i += 256) {   // w2: [co][tap] -> wP[tap*16+co]
        int co = i & 15, tap = i >> 4;
        float wgt = w2[co * 162 + tap];
        wP[i] = f2pack(wgt, wgt);
    }
    for (int i = tid; i < 5832; i += 256) {   // 18*18*18 float4 chunks
        int ci  = i / 324;
        int rem = i - ci * 324;
        int yy = rem / 18, xx = rem - yy * 18;
        int gh = h0 + yy - 1, gw = w0 + xx - 1;
        float4 v = make_float4(0.f, 0.f, 0.f, 0.f);
        if ((unsigned)gh < 128u && (unsigned)gw < 128u) {
            const float* srcp = (ci < 16)
                ? (g_psps1 + ((((size_t)n * 16 + ci)        * 128 + gh) * 128 + gw) * TT + t0)
                : (g_psp0  + ((((size_t)n * 2  + (ci - 16)) * 128 + gh) * 128 + gw) * TT + t0);
            v = *(const float4*)srcp;
        }
        *(float4*)&tile[(size_t)i * 4] = v;
    }
    __syncthreads();

    ull acc2[32];               // acc2[(pix*8 + co)*2 + tpair]
#pragma unroll
    for (int i = 0; i < 32; i++) acc2[i] = 0ull;

    for (int ci = 0; ci < 18; ci++) {
#pragma unroll
        for (int ky = 0; ky < 3; ky++)
#pragma unroll
            for (int kx = 0; kx < 3; kx++) {
                ulonglong2 inA = *(const ulonglong2*)
                    &tile[(((ci * 18) + (y + ky)) * 18 + (x + kx)) * 4];
                ulonglong2 inB = *(const ulonglong2*)
                    &tile[(((ci * 18) + (y + ky)) * 18 + (x + 8 + kx)) * 4];
                const ulonglong2* wrow =
                    (const ulonglong2*)&wP[(ci * 9 + ky * 3 + kx) * 16 + cg * 8];
                ulonglong2 w01 = wrow[0], w23 = wrow[1], w45 = wrow[2], w67 = wrow[3];
                acc2[ 0] = f2fma(inA.x, w01.x, acc2[ 0]);
                acc2[ 1] = f2fma(inA.y, w01.x, acc2[ 1]);
                acc2[ 2] = f2fma(inA.x, w01.y, acc2[ 2]);
                acc2[ 3] = f2fma(inA.y, w01.y, acc2[ 3]);
                acc2[ 4] = f2fma(inA.x, w23.x, acc2[ 4]);
                acc2[ 5] = f2fma(inA.y, w23.x, acc2[ 5]);
                acc2[ 6] = f2fma(inA.x, w23.y, acc2[ 6]);
                acc2[ 7] = f2fma(inA.y, w23.y, acc2[ 7]);
                acc2[ 8] = f2fma(inA.x, w45.x, acc2[ 8]);
                acc2[ 9] = f2fma(inA.y, w45.x, acc2[ 9]);
                acc2[10] = f2fma(inA.x, w45.y, acc2[10]);
                acc2[11] = f2fma(inA.y, w45.y, acc2[11]);
                acc2[12] = f2fma(inA.x, w67.x, acc2[12]);
                acc2[13] = f2fma(inA.y, w67.x, acc2[13]);
                acc2[14] = f2fma(inA.x, w67.y, acc2[14]);
                acc2[15] = f2fma(inA.y, w67.y, acc2[15]);
                acc2[16] = f2fma(inB.x, w01.x, acc2[16]);
                acc2[17] = f2fma(inB.y, w01.x, acc2[17]);
                acc2[18] = f2fma(inB.x, w01.y, acc2[18]);
                acc2[19] = f2fma(inB.y, w01.y, acc2[19]);
                acc2[20] = f2fma(inB.x, w23.x, acc2[20]);
                acc2[21] = f2fma(inB.y, w23.x, acc2[21]);
                acc2[22] = f2fma(inB.x, w23.y, acc2[22]);
                acc2[23] = f2fma(inB.y, w23.y, acc2[23]);
                acc2[24] = f2fma(inB.x, w45.x, acc2[24]);
                acc2[25] = f2fma(inB.y, w45.x, acc2[25]);
                acc2[26] = f2fma(inB.x, w45.y, acc2[26]);
                acc2[27] = f2fma(inB.y, w45.y, acc2[27]);
                acc2[28] = f2fma(inB.x, w67.x, acc2[28]);
                acc2[29] = f2fma(inB.y, w67.x, acc2[29]);
                acc2[30] = f2fma(inB.x, w67.y, acc2[30]);
                acc2[31] = f2fma(inB.y, w67.y, acc2[31]);
            }
    }

    int gh = h0 + y;
#pragma unroll
    for (int pix = 0; pix < 2; pix++) {
        int gw = w0 + x + pix * 8;
#pragma unroll
        for (int c = 0; c < 8; c++) {
            int co = cg * 8 + c;
            size_t o = ((((size_t)n * 16 + co) * 128 + gh) * 128 + gw) * TT + t0;
            *(ulonglong2*)&g_p2[o] =
                make_ulonglong2(acc2[(pix*8 + c)*2], acc2[(pix*8 + c)*2 + 1]);
        }
    }
}

// ---------------- fused: spike2 (theta=5) + psp(s2,srm2) + conv3 (1x1) ------
#define SM_STRIDE 36
__global__ void __launch_bounds__(256, 2) k_l3(const float* __restrict__ w3,
                                               float* __restrict__ out) {
    __shared__ float sm_in[18 * 16 * SM_STRIDE];   // [ci][p][t], padded stride
    __shared__ ull   wS[18 * 32];                  // [ci][co] (w,w) pairs

    int tid = threadIdx.x;
    int n = blockIdx.z, h = blockIdx.y, w0 = blockIdx.x * 16;

    for (int i = tid; i < 576; i += 256) {         // w3: [co][ci]
        int co = i & 31, ci = i >> 5;
        float wgt = w3[co * 18 + ci];
        wS[i] = f2pack(wgt, wgt);                  // wS[ci*32+co]
    }

    // ---- phase 1: spike2 + psp(s2) per (pixel, channel) ----
    {
        int p  = tid & 15;
        int ci = tid >> 4;
        const float4* src = (const float4*)(g_p2 +
            ((((size_t)n * 16 + ci) * 128 + h) * 128 + (w0 + p)) * TT);
        float pv[TT];
#pragma unroll
        for (int v = 0; v < 8; v++) {
            float4 f = src[v];
            pv[4*v] = f.x; pv[4*v+1] = f.y; pv[4*v+2] = f.z; pv[4*v+3] = f.w;
        }
        float rc[32];
#pragma unroll
        for (int d = 1; d < 32; d++) rc[d] = g_refc2[d];
        float r[TT];
#pragma unroll
        for (int t = 0; t < TT; t++) r[t] = 0.f;
        float A = 0.f, B = 0.f;
#pragma unroll
        for (int t = 0; t < TT; t++) {
            float u = pv[t] + r[t];
            bool sp = (u >= 5.0f);
            B = Q2F * (B + A);
            A = Q2F * A + (sp ? 1.0f : 0.0f);
            pv[t] = CS2F * B;                  // psp(s2)
            if (sp) {
#pragma unroll
                for (int d = 1; d < 32; d++)
                    if (t + d < TT) r[t + d] += rc[d];
            }
        }
        float* drow = &sm_in[(ci * 16 + p) * SM_STRIDE];
#pragma unroll
        for (int v = 0; v < 8; v++)
            *(float4*)&drow[4*v] = make_float4(pv[4*v], pv[4*v+1], pv[4*v+2], pv[4*v+3]);

        if (tid < 32) {                        // psp0 channels 16,17
            int pp = tid & 15, c = tid >> 4;
            const float4* s2 = (const float4*)(g_psp0 +
                (((size_t)n * 2 + c) * 16384 + h * 128 + (w0 + pp)) * TT);
            float* dr = &sm_in[((16 + c) * 16 + pp) * SM_STRIDE];
#pragma unroll
            for (int v = 0; v < 8; v++) *(float4*)&dr[4*v] = s2[v];
        }
    }
    __syncthreads();

    // ---- phase 2: 1x1 conv (18 -> 32), f32x2 (R5 dataflow) ----
    int p  = tid >> 4;
    int q  = tid & 15;
    int cohalf = q >> 3;
    int t0 = (q & 7) * 4;

    ull acc2[32];
#pragma unroll
    for (int i = 0; i < 32; i++) acc2[i] = 0ull;

#pragma unroll
    for (int ci = 0; ci < 18; ci++) {
        ulonglong2 in2 = *(const ulonglong2*)&sm_in[(ci * 16 + p) * SM_STRIDE + t0];
#pragma unroll
        for (int cp = 0; cp < 8; cp++) {
            ulonglong2 wv = *(const ulonglong2*)&wS[ci * 32 + cohalf * 16 + cp * 2];
            acc2[cp*4+0] = f2fma(in2.x, wv.x, acc2[cp*4+0]);
            acc2[cp*4+1] = f2fma(in2.y, wv.x, acc2[cp*4+1]);
            acc2[cp*4+2] = f2fma(in2.x, wv.y, acc2[cp*4+2]);
            acc2[cp*4+3] = f2fma(in2.y, wv.y, acc2[cp*4+3]);
        }
    }

    int hw = h * 128 + w0 + p;
#pragma unroll
    for (int cp = 0; cp < 8; cp++) {
#pragma unroll
        for (int s = 0; s < 2; s++) {
            int co = cohalf * 16 + cp * 2 + s;
            size_t o = (((size_t)n * 32 + co) * 16384 + hw) * TT + t0;
            *(ulonglong2*)(out + o) = make_ulonglong2(acc2[cp*4 + 2*s], acc2[cp*4 + 2*s + 1]);
        }
    }
}

// ---------------- launcher ---------------------------------------------------
extern "C" void kernel_launch(void* const* d_in, const int* in_sizes, int n_in,
                              void* d_out, int out_size) {
    const float* spikeIn = (const float*)d_in[0];
    const float* w1 = (const float*)d_in[1];
    const float* w2 = (const float*)d_in[2];
    const float* w3 = (const float*)d_in[3];
    float* out = (float*)d_out;

    const int l1_smem    = 2 * 18 * 18 * L1_RS * 4;      // 93,312 B
    const int conv2_smem = 23328 * 4 + 2592 * 8;         // 114,048 B
    cudaFuncSetAttribute(k_l1,    cudaFuncAttributeMaxDynamicSharedMemorySize, l1_smem);
    cudaFuncSetAttribute(k_conv2, cudaFuncAttributeMaxDynamicSharedMemorySize, conv2_smem);

    k_init<<<1, 32>>>();
    k_psp0<<<512, 256>>>(spikeIn);
    dim3 g1(8, 8, 4);
    k_l1<<<g1, 256, l1_smem>>>(w1);
    dim3 g2(8, 8, 32);
    k_conv2<<<g2, 256, conv2_smem>>>(w2);
    dim3 g3(8, 128, 4);
    k_l3<<<g3, 256>>>(w3, out);
}

// round 10
// speedup vs baseline: 1.3193x; 1.0626x over previous
#include <cuda_runtime.h>

#define NBATCH 4
#define HH 128
#define WW 128
#define TT 32

typedef unsigned long long ull;

// ---------------- f32x2 packed-math helpers (sm_103a) -----------------------
__device__ __forceinline__ ull f2fma(ull a, ull b, ull c) {
    ull d;
    asm("fma.rn.f32x2 %0, %1, %2, %3;" : "=l"(d) : "l"(a), "l"(b), "l"(c));
    return d;
}
__device__ __forceinline__ ull f2pack(float lo, float hi) {
    ull r; asm("mov.b64 %0, {%1, %2};" : "=l"(r) : "f"(lo), "f"(hi)); return r;
}
__device__ __forceinline__ void f2unpack(ull v, float& lo, float& hi) {
    asm("mov.b64 {%0, %1}, %2;" : "=f"(lo), "=f"(hi) : "l"(v));
}

// ---------------- tables + scratch (device globals: no runtime allocation) ----
static __device__ float g_srm0[32];
static __device__ float g_refc1[32];
static __device__ float g_refc2[32];

static __device__ float g_psp0 [(size_t)NBATCH * 2  * HH * WW * TT]; //  16 MB
static __device__ float g_psps1[(size_t)NBATCH * 16 * HH * WW * TT]; // 128 MB
static __device__ float g_p2   [(size_t)NBATCH * 16 * HH * WW * TT]; // 128 MB

#define Q1F  0.60653065971263342f  /* exp(-1/2)  */
#define Q2F  0.77880078307140487f  /* exp(-1/4)  */
#define CS1F 1.3591409142295226f   /* e/2 : srm1[k] = CS1*k*Q1^k */
#define CS2F 0.67957045711476131f  /* e/4 : srm2[k] = CS2*k*Q2^k */

// ---------------- init: alpha-kernel tables (match reference truncation) -----
__global__ void k_init() {
    int t = threadIdx.x;
    if (t < 32) {
        double td = (double)t;
        double v0 = td * exp(1.0 - td);                      // srm0 (tau=1), trunc@18
        g_srm0[t]  = (t < 18) ? (float)v0 : 0.0f;
        double r1 = -3.0 * td * exp(1.0 - td);               // refk layer1, trunc@19
        g_refc1[t] = (t < 19) ? (float)r1 : 0.0f;
        double r2 = -5.0 * (td * 0.5) * exp(1.0 - td * 0.5); // refk layer2, full 32
        g_refc2[t] = (float)r2;
    }
}

// ---------------- psp0: temporal filter of binary input (truncated table) ---
__global__ void __launch_bounds__(256) k_psp0(const float* __restrict__ in) {
    int gid = blockIdx.x * blockDim.x + threadIdx.x;   // (n,c,h,w) : 131072
    const float4* src = (const float4*)(in + (size_t)gid * TT);
    float x[TT];
#pragma unroll
    for (int v = 0; v < 8; v++) {
        float4 f = src[v];
        x[4*v] = f.x; x[4*v+1] = f.y; x[4*v+2] = f.z; x[4*v+3] = f.w;
    }
    float s0[18];
#pragma unroll
    for (int k = 0; k < 18; k++) s0[k] = g_srm0[k];
    float y[TT];
#pragma unroll
    for (int t = 0; t < TT; t++) {
        float a = 0.f;
#pragma unroll
        for (int k = 1; k < 18; k++)
            if (k <= t) a += x[t - k] * s0[k];
        y[t] = a;
    }
    float4* dst = (float4*)(g_psp0 + (size_t)gid * TT);
#pragma unroll
    for (int v = 0; v < 8; v++)
        dst[v] = make_float4(y[4*v], y[4*v+1], y[4*v+2], y[4*v+3]);
}

// ---------------- fused: conv1 (3x3, 2->16) + spike1 + psp(s1,srm1) ---------
// smem-tiled: block = 16x16 pixels; per-thread loop over 16 co.
#define L1_RS 36
__global__ void __launch_bounds__(256) k_l1(const float* __restrict__ w1) {
    extern __shared__ float tile[];      // [2][18][18][L1_RS]  (ci, yy, xx, t)
    __shared__ float wL[288];

    int tid = threadIdx.x;
    int w0 = blockIdx.x * 16, h0 = blockIdx.y * 16;
    int n  = blockIdx.z;

    for (int i = tid; i < 288; i += 256) wL[i] = w1[i];
    for (int i = tid; i < 5184; i += 256) {      // 2*18*18*8 float4 chunks
        int ci  = i / 2592;
        int rem = i - ci * 2592;
        int yy  = rem / 144;
        int r2  = rem - yy * 144;
        int xx  = r2 >> 3, v = r2 & 7;
        int gh = h0 + yy - 1, gw = w0 + xx - 1;
        float4 val = make_float4(0.f, 0.f, 0.f, 0.f);
        if ((unsigned)gh < 128u && (unsigned)gw < 128u)
            val = *(const float4*)(g_psp0 +
                ((((size_t)n * 2 + ci) * 128 + gh) * 128 + gw) * TT + v * 4);
        *(float4*)&tile[((ci * 18 + yy) * 18 + xx) * L1_RS + v * 4] = val;
    }
    __syncthreads();

    int x = tid & 15, y = tid >> 4;
    int gh = h0 + y, gw = w0 + x;

    float rc[19];
#pragma unroll
    for (int d = 1; d < 19; d++) rc[d] = g_refc1[d];

    for (int co = 0; co < 16; co++) {
        ull acc2[16];
#pragma unroll
        for (int i = 0; i < 16; i++) acc2[i] = 0ull;

#pragma unroll
        for (int ci = 0; ci < 2; ci++)
#pragma unroll
            for (int ky = 0; ky < 3; ky++)
#pragma unroll
                for (int kx = 0; kx < 3; kx++) {
                    float wgt = wL[co * 18 + ci * 9 + ky * 3 + kx];
                    ull wp = f2pack(wgt, wgt);
                    const ulonglong2* p = (const ulonglong2*)
                        &tile[((ci * 18 + (y + ky)) * 18 + (x + kx)) * L1_RS];
#pragma unroll
                    for (int v = 0; v < 8; v++) {
                        ulonglong2 f = p[v];
                        acc2[2*v]   = f2fma(f.x, wp, acc2[2*v]);
                        acc2[2*v+1] = f2fma(f.y, wp, acc2[2*v+1]);
                    }
                }

        float acc[TT];
#pragma unroll
        for (int v = 0; v < 16; v++) f2unpack(acc2[v], acc[2*v], acc[2*v+1]);

        // spike1 (theta=3, refractory len 19, exact replay) + psp1 recurrence
        float r[TT];
#pragma unroll
        for (int t = 0; t < TT; t++) r[t] = 0.f;
        float A = 0.f, B = 0.f;
#pragma unroll
        for (int t = 0; t < TT; t++) {
            float u = acc[t] + r[t];
            bool sp = (u >= 3.0f);
            B = Q1F * (B + A);
            A = Q1F * A + (sp ? 1.0f : 0.0f);
            acc[t] = CS1F * B;             // psp(s1)
            if (sp) {
#pragma unroll
                for (int d = 1; d < 19; d++)
                    if (t + d < TT) r[t + d] += rc[d];
            }
        }

        float4* dst = (float4*)(g_psps1 +
            ((((size_t)n * 16 + co) * 128 + gh) * 128 + gw) * TT);
#pragma unroll
        for (int v = 0; v < 8; v++)
            dst[v] = make_float4(acc[4*v], acc[4*v+1], acc[4*v+2], acc[4*v+3]);
    }
}

// ---------------- conv2 (3x3, 18->16), smem tiled, f32x2, 512-thread --------
// block = 512 thr: 16x16 pixels x 2 co-groups; thread = 1 pixel x 8 co x 4 t.
// 2 blocks/SM -> 32 warps/SM; regs ~60.
__global__ void __launch_bounds__(512, 2) k_conv2(const float* __restrict__ w2) {
    extern __shared__ float smem[];
    float* tile = smem;                       // [18][18][18][4]  (ci, yy, xx, tt)
    ull*   wP   = (ull*)(smem + 23328);       // [162 taps][16 co] (w,w) pairs

    int tid = threadIdx.x;
    int cg = tid >> 8;                        // co-group: 0 -> co 0-7, 1 -> 8-15
    int p  = tid & 255;
    int x = p & 15, y = p >> 4;
    int w0 = blockIdx.x * 16, h0 = blockIdx.y * 16;
    int bz = blockIdx.z;
    int n = bz >> 3, t0 = (bz & 7) * 4;

    for (int i = tid; i < 2592; i += 512) {   // w2: [co][tap] -> wP[tap*16+co]
        int co = i & 15, tap = i >> 4;
        float wgt = w2[co * 162 + tap];
        wP[i] = f2pack(wgt, wgt);
    }
    for (int i = tid; i < 5832; i += 512) {   // 18*18*18 float4 chunks
        int ci  = i / 324;
        int rem = i - ci * 324;
        int yy = rem / 18, xx = rem - yy * 18;
        int gh = h0 + yy - 1, gw = w0 + xx - 1;
        float4 v = make_float4(0.f, 0.f, 0.f, 0.f);
        if ((unsigned)gh < 128u && (unsigned)gw < 128u) {
            const float* srcp = (ci < 16)
                ? (g_psps1 + ((((size_t)n * 16 + ci)        * 128 + gh) * 128 + gw) * TT + t0)
                : (g_psp0  + ((((size_t)n * 2  + (ci - 16)) * 128 + gh) * 128 + gw) * TT + t0);
            v = *(const float4*)srcp;
        }
        *(float4*)&tile[(size_t)i * 4] = v;
    }
    __syncthreads();

    ull acc2[16];                // acc2[c*2 + tpair], c = co within group
#pragma unroll
    for (int i = 0; i < 16; i++) acc2[i] = 0ull;

    for (int ci = 0; ci < 18; ci++) {
#pragma unroll
        for (int ky = 0; ky < 3; ky++)
#pragma unroll
            for (int kx = 0; kx < 3; kx++) {
                ulonglong2 in2 = *(const ulonglong2*)
                    &tile[(((ci * 18) + (y + ky)) * 18 + (x + kx)) * 4];
                const ulonglong2* wrow =
                    (const ulonglong2*)&wP[(ci * 9 + ky * 3 + kx) * 16 + cg * 8];
                ulonglong2 w01 = wrow[0], w23 = wrow[1], w45 = wrow[2], w67 = wrow[3];
                acc2[ 0] = f2fma(in2.x, w01.x, acc2[ 0]);
                acc2[ 1] = f2fma(in2.y, w01.x, acc2[ 1]);
                acc2[ 2] = f2fma(in2.x, w01.y, acc2[ 2]);
                acc2[ 3] = f2fma(in2.y, w01.y, acc2[ 3]);
                acc2[ 4] = f2fma(in2.x, w23.x, acc2[ 4]);
                acc2[ 5] = f2fma(in2.y, w23.x, acc2[ 5]);
                acc2[ 6] = f2fma(in2.x, w23.y, acc2[ 6]);
                acc2[ 7] = f2fma(in2.y, w23.y, acc2[ 7]);
                acc2[ 8] = f2fma(in2.x, w45.x, acc2[ 8]);
                acc2[ 9] = f2fma(in2.y, w45.x, acc2[ 9]);
                acc2[10] = f2fma(in2.x, w45.y, acc2[10]);
                acc2[11] = f2fma(in2.y, w45.y, acc2[11]);
                acc2[12] = f2fma(in2.x, w67.x, acc2[12]);
                acc2[13] = f2fma(in2.y, w67.x, acc2[13]);
                acc2[14] = f2fma(in2.x, w67.y, acc2[14]);
                acc2[15] = f2fma(in2.y, w67.y, acc2[15]);
            }
    }

    int gh = h0 + y, gw = w0 + x;
#pragma unroll
    for (int c = 0; c < 8; c++) {
        int co = cg * 8 + c;
        size_t o = ((((size_t)n * 16 + co) * 128 + gh) * 128 + gw) * TT + t0;
        *(ulonglong2*)&g_p2[o] = make_ulonglong2(acc2[c*2], acc2[c*2 + 1]);
    }
}

// ---------------- fused: spike2 (theta=5) + psp(s2,srm2) + conv3 (1x1) ------
#define SM_STRIDE 36
__global__ void __launch_bounds__(256, 2) k_l3(const float* __restrict__ w3,
                                               float* __restrict__ out) {
    __shared__ float sm_in[18 * 16 * SM_STRIDE];   // [ci][p][t], padded stride
    __shared__ ull   wS[18 * 32];                  // [ci][co] (w,w) pairs

    int tid = threadIdx.x;
    int n = blockIdx.z, h = blockIdx.y, w0 = blockIdx.x * 16;

    for (int i = tid; i < 576; i += 256) {         // w3: [co][ci]
        int co = i & 31, ci = i >> 5;
        float wgt = w3[co * 18 + ci];
        wS[i] = f2pack(wgt, wgt);                  // wS[ci*32+co]
    }

    // ---- phase 1: spike2 + psp(s2) per (pixel, channel), exact replay ----
    {
        int p  = tid & 15;
        int ci = tid >> 4;
        const float4* src = (const float4*)(g_p2 +
            ((((size_t)n * 16 + ci) * 128 + h) * 128 + (w0 + p)) * TT);
        float pv[TT];
#pragma unroll
        for (int v = 0; v < 8; v++) {
            float4 f = src[v];
            pv[4*v] = f.x; pv[4*v+1] = f.y; pv[4*v+2] = f.z; pv[4*v+3] = f.w;
        }
        float rc[32];
#pragma unroll
        for (int d = 1; d < 32; d++) rc[d] = g_refc2[d];
        float r[TT];
#pragma unroll
        for (int t = 0; t < TT; t++) r[t] = 0.f;
        float A = 0.f, B = 0.f;
#pragma unroll
        for (int t = 0; t < TT; t++) {
            float u = pv[t] + r[t];
            bool sp = (u >= 5.0f);
            B = Q2F * (B + A);
            A = Q2F * A + (sp ? 1.0f : 0.0f);
            pv[t] = CS2F * B;                  // psp(s2)
            if (sp) {
#pragma unroll
                for (int d = 1; d < 32; d++)
                    if (t + d < TT) r[t + d] += rc[d];
            }
        }
        float* drow = &sm_in[(ci * 16 + p) * SM_STRIDE];
#pragma unroll
        for (int v = 0; v < 8; v++)
            *(float4*)&drow[4*v] = make_float4(pv[4*v], pv[4*v+1], pv[4*v+2], pv[4*v+3]);

        if (tid < 32) {                        // psp0 channels 16,17
            int pp = tid & 15, c = tid >> 4;
            const float4* s2 = (const float4*)(g_psp0 +
                (((size_t)n * 2 + c) * 16384 + h * 128 + (w0 + pp)) * TT);
            float* dr = &sm_in[((16 + c) * 16 + pp) * SM_STRIDE];
#pragma unroll
            for (int v = 0; v < 8; v++) *(float4*)&dr[4*v] = s2[v];
        }
    }
    __syncthreads();

    // ---- phase 2: 1x1 conv (18 -> 32), f32x2 ----
    int p  = tid >> 4;
    int q  = tid & 15;
    int cohalf = q >> 3;
    int t0 = (q & 7) * 4;

    ull acc2[32];
#pragma unroll
    for (int i = 0; i < 32; i++) acc2[i] = 0ull;

#pragma unroll
    for (int ci = 0; ci < 18; ci++) {
        ulonglong2 in2 = *(const ulonglong2*)&sm_in[(ci * 16 + p) * SM_STRIDE + t0];
#pragma unroll
        for (int cp = 0; cp < 8; cp++) {
            ulonglong2 wv = *(const ulonglong2*)&wS[ci * 32 + cohalf * 16 + cp * 2];
            acc2[cp*4+0] = f2fma(in2.x, wv.x, acc2[cp*4+0]);
            acc2[cp*4+1] = f2fma(in2.y, wv.x, acc2[cp*4+1]);
            acc2[cp*4+2] = f2fma(in2.x, wv.y, acc2[cp*4+2]);
            acc2[cp*4+3] = f2fma(in2.y, wv.y, acc2[cp*4+3]);
        }
    }

    int hw = h * 128 + w0 + p;
#pragma unroll
    for (int cp = 0; cp < 8; cp++) {
#pragma unroll
        for (int s = 0; s < 2; s++) {
            int co = cohalf * 16 + cp * 2 + s;
            size_t o = (((size_t)n * 32 + co) * 16384 + hw) * TT + t0;
            *(ulonglong2*)(out + o) = make_ulonglong2(acc2[cp*4 + 2*s], acc2[cp*4 + 2*s + 1]);
        }
    }
}

// ---------------- launcher ---------------------------------------------------
extern "C" void kernel_launch(void* const* d_in, const int* in_sizes, int n_in,
                              void* d_out, int out_size) {
    const float* spikeIn = (const float*)d_in[0];
    const float* w1 = (const float*)d_in[1];
    const float* w2 = (const float*)d_in[2];
    const float* w3 = (const float*)d_in[3];
    float* out = (float*)d_out;

    const int l1_smem    = 2 * 18 * 18 * L1_RS * 4;      // 93,312 B
    const int conv2_smem = 23328 * 4 + 2592 * 8;         // 114,048 B
    cudaFuncSetAttribute(k_l1,    cudaFuncAttributeMaxDynamicSharedMemorySize, l1_smem);
    cudaFuncSetAttribute(k_conv2, cudaFuncAttributeMaxDynamicSharedMemorySize, conv2_smem);

    k_init<<<1, 32>>>();
    k_psp0<<<512, 256>>>(spikeIn);
    dim3 g1(8, 8, 4);
    k_l1<<<g1, 256, l1_smem>>>(w1);
    dim3 g2(8, 8, 32);
    k_conv2<<<g2, 512, conv2_smem>>>(w2);
    dim3 g3(8, 128, 4);
    k_l3<<<g3, 256>>>(w3, out);
}

// round 11
// speedup vs baseline: 1.7042x; 1.2918x over previous
#include <cuda_runtime.h>

#define NBATCH 4
#define HH 128
#define WW 128
#define TT 32

typedef unsigned long long ull;

// ---------------- f32x2 packed-math helpers (sm_103a) -----------------------
__device__ __forceinline__ ull f2fma(ull a, ull b, ull c) {
    ull d;
    asm("fma.rn.f32x2 %0, %1, %2, %3;" : "=l"(d) : "l"(a), "l"(b), "l"(c));
    return d;
}
__device__ __forceinline__ ull f2pack(float lo, float hi) {
    ull r; asm("mov.b64 %0, {%1, %2};" : "=l"(r) : "f"(lo), "f"(hi)); return r;
}
__device__ __forceinline__ void f2unpack(ull v, float& lo, float& hi) {
    asm("mov.b64 {%0, %1}, %2;" : "=f"(lo), "=f"(hi) : "l"(v));
}

// ---------------- tables + scratch (device globals: no runtime allocation) ----
static __device__ float g_srm0[32];
static __device__ float g_refc1[32];
static __device__ float g_refc2[32];

static __device__ float g_psp0 [(size_t)NBATCH * 2  * HH * WW * TT]; //  16 MB
static __device__ float g_p1   [(size_t)NBATCH * 16 * HH * WW * TT]; // 128 MB
static __device__ float g_psps1[(size_t)NBATCH * 16 * HH * WW * TT]; // 128 MB
static __device__ float g_p2   [(size_t)NBATCH * 16 * HH * WW * TT]; // 128 MB

#define Q1F  0.60653065971263342f  /* exp(-1/2)  */
#define Q2F  0.77880078307140487f  /* exp(-1/4)  */
#define CS1F 1.3591409142295226f   /* e/2 : srm1[k] = CS1*k*Q1^k */
#define CS2F 0.67957045711476131f  /* e/4 : srm2[k] = CS2*k*Q2^k */

// ---------------- init: alpha-kernel tables (match reference truncation) -----
__global__ void k_init() {
    int t = threadIdx.x;
    if (t < 32) {
        double td = (double)t;
        double v0 = td * exp(1.0 - td);                      // srm0 (tau=1), trunc@18
        g_srm0[t]  = (t < 18) ? (float)v0 : 0.0f;
        double r1 = -3.0 * td * exp(1.0 - td);               // refk layer1, trunc@19
        g_refc1[t] = (t < 19) ? (float)r1 : 0.0f;
        double r2 = -5.0 * (td * 0.5) * exp(1.0 - td * 0.5); // refk layer2, full 32
        g_refc2[t] = (float)r2;
    }
}

// ---------------- psp0: temporal filter of binary input (truncated table) ---
__global__ void __launch_bounds__(256) k_psp0(const float* __restrict__ in) {
    int gid = blockIdx.x * blockDim.x + threadIdx.x;   // (n,c,h,w) : 131072
    const float4* src = (const float4*)(in + (size_t)gid * TT);
    float x[TT];
#pragma unroll
    for (int v = 0; v < 8; v++) {
        float4 f = src[v];
        x[4*v] = f.x; x[4*v+1] = f.y; x[4*v+2] = f.z; x[4*v+3] = f.w;
    }
    float s0[18];
#pragma unroll
    for (int k = 0; k < 18; k++) s0[k] = g_srm0[k];
    float y[TT];
#pragma unroll
    for (int t = 0; t < TT; t++) {
        float a = 0.f;
#pragma unroll
        for (int k = 1; k < 18; k++)
            if (k <= t) a += x[t - k] * s0[k];
        y[t] = a;
    }
    float4* dst = (float4*)(g_psp0 + (size_t)gid * TT);
#pragma unroll
    for (int v = 0; v < 8; v++)
        dst[v] = make_float4(y[4*v], y[4*v+1], y[4*v+2], y[4*v+3]);
}

// ---------------- l1a: conv1 (3x3, 2->16) membrane, conv2-style dataflow ----
// block = 512 thr: 16x16 pixels x 2 co-groups; thread = 1 pixel x 8 co x 4 t.
// Same f2fma tap order (ci,ky,kx) as old fused l1 -> bit-identical u values.
__global__ void __launch_bounds__(512, 2) k_l1a(const float* __restrict__ w1) {
    __shared__ float tile[2 * 18 * 18 * 4];   // (ci, yy, xx, tt)  10,368 B
    __shared__ ull   wP[18 * 16];             // [18 taps][16 co] (w,w) pairs

    int tid = threadIdx.x;
    int cg = tid >> 8;                        // co-group: 0 -> co 0-7, 1 -> 8-15
    int p  = tid & 255;
    int x = p & 15, y = p >> 4;
    int w0 = blockIdx.x * 16, h0 = blockIdx.y * 16;
    int bz = blockIdx.z;
    int n = bz >> 3, t0 = (bz & 7) * 4;

    if (tid < 288) {                          // w1: [co][ci][ky][kx]
        int co = tid & 15, tap = tid >> 4;
        float wgt = w1[co * 18 + tap];
        wP[tid] = f2pack(wgt, wgt);
    }
    for (int i = tid; i < 648; i += 512) {    // 2*18*18 float4 chunks
        int ci  = i / 324;
        int rem = i - ci * 324;
        int yy = rem / 18, xx = rem - yy * 18;
        int gh = h0 + yy - 1, gw = w0 + xx - 1;
        float4 v = make_float4(0.f, 0.f, 0.f, 0.f);
        if ((unsigned)gh < 128u && (unsigned)gw < 128u)
            v = *(const float4*)(g_psp0 +
                ((((size_t)n * 2 + ci) * 128 + gh) * 128 + gw) * TT + t0);
        *(float4*)&tile[(size_t)i * 4] = v;
    }
    __syncthreads();

    ull acc2[16];                // acc2[c*2 + tpair], c = co within group
#pragma unroll
    for (int i = 0; i < 16; i++) acc2[i] = 0ull;

#pragma unroll
    for (int ci = 0; ci < 2; ci++)
#pragma unroll
        for (int ky = 0; ky < 3; ky++)
#pragma unroll
            for (int kx = 0; kx < 3; kx++) {
                ulonglong2 in2 = *(const ulonglong2*)
                    &tile[(((ci * 18) + (y + ky)) * 18 + (x + kx)) * 4];
                const ulonglong2* wrow =
                    (const ulonglong2*)&wP[(ci * 9 + ky * 3 + kx) * 16 + cg * 8];
                ulonglong2 w01 = wrow[0], w23 = wrow[1], w45 = wrow[2], w67 = wrow[3];
                acc2[ 0] = f2fma(in2.x, w01.x, acc2[ 0]);
                acc2[ 1] = f2fma(in2.y, w01.x, acc2[ 1]);
                acc2[ 2] = f2fma(in2.x, w01.y, acc2[ 2]);
                acc2[ 3] = f2fma(in2.y, w01.y, acc2[ 3]);
                acc2[ 4] = f2fma(in2.x, w23.x, acc2[ 4]);
                acc2[ 5] = f2fma(in2.y, w23.x, acc2[ 5]);
                acc2[ 6] = f2fma(in2.x, w23.y, acc2[ 6]);
                acc2[ 7] = f2fma(in2.y, w23.y, acc2[ 7]);
                acc2[ 8] = f2fma(in2.x, w45.x, acc2[ 8]);
                acc2[ 9] = f2fma(in2.y, w45.x, acc2[ 9]);
                acc2[10] = f2fma(in2.x, w45.y, acc2[10]);
                acc2[11] = f2fma(in2.y, w45.y, acc2[11]);
                acc2[12] = f2fma(in2.x, w67.x, acc2[12]);
                acc2[13] = f2fma(in2.y, w67.x, acc2[13]);
                acc2[14] = f2fma(in2.x, w67.y, acc2[14]);
                acc2[15] = f2fma(in2.y, w67.y, acc2[15]);
            }

    int gh = h0 + y, gw = w0 + x;
#pragma unroll
    for (int c = 0; c < 8; c++) {
        int co = cg * 8 + c;
        size_t o = ((((size_t)n * 16 + co) * 128 + gh) * 128 + gw) * TT + t0;
        *(ulonglong2*)&g_p1[o] = make_ulonglong2(acc2[c*2], acc2[c*2 + 1]);
    }
}

// ---------------- l1b: spike1 (theta=3, exact replay) + psp(s1,srm1) --------
__global__ void __launch_bounds__(256) k_l1b() {
    int gid = blockIdx.x * 256 + threadIdx.x;          // (n,co,h,w) : 2^20
    float acc[TT];
    const float4* src = (const float4*)(g_p1 + (size_t)gid * TT);
#pragma unroll
    for (int v = 0; v < 8; v++) {
        float4 f = src[v];
        acc[4*v] = f.x; acc[4*v+1] = f.y; acc[4*v+2] = f.z; acc[4*v+3] = f.w;
    }

    float rc[19];
#pragma unroll
    for (int d = 1; d < 19; d++) rc[d] = g_refc1[d];
    float r[TT];
#pragma unroll
    for (int t = 0; t < TT; t++) r[t] = 0.f;
    float A = 0.f, B = 0.f;
#pragma unroll
    for (int t = 0; t < TT; t++) {
        float u = acc[t] + r[t];
        bool sp = (u >= 3.0f);
        B = Q1F * (B + A);
        A = Q1F * A + (sp ? 1.0f : 0.0f);
        acc[t] = CS1F * B;                 // psp(s1)
        if (sp) {
#pragma unroll
            for (int d = 1; d < 19; d++)
                if (t + d < TT) r[t + d] += rc[d];
        }
    }

    float4* dst = (float4*)(g_psps1 + (size_t)gid * TT);
#pragma unroll
    for (int v = 0; v < 8; v++)
        dst[v] = make_float4(acc[4*v], acc[4*v+1], acc[4*v+2], acc[4*v+3]);
}

// ---------------- conv2 (3x3, 18->16), smem tiled, f32x2, 512-thread --------
__global__ void __launch_bounds__(512, 2) k_conv2(const float* __restrict__ w2) {
    extern __shared__ float smem[];
    float* tile = smem;                       // [18][18][18][4]  (ci, yy, xx, tt)
    ull*   wP   = (ull*)(smem + 23328);       // [162 taps][16 co] (w,w) pairs

    int tid = threadIdx.x;
    int cg = tid >> 8;                        // co-group: 0 -> co 0-7, 1 -> 8-15
    int p  = tid & 255;
    int x = p & 15, y = p >> 4;
    int w0 = blockIdx.x * 16, h0 = blockIdx.y * 16;
    int bz = blockIdx.z;
    int n = bz >> 3, t0 = (bz & 7) * 4;

    for (int i = tid; i < 2592; i += 512) {   // w2: [co][tap] -> wP[tap*16+co]
        int co = i & 15, tap = i >> 4;
        float wgt = w2[co * 162 + tap];
        wP[i] = f2pack(wgt, wgt);
    }
    for (int i = tid; i < 5832; i += 512) {   // 18*18*18 float4 chunks
        int ci  = i / 324;
        int rem = i - ci * 324;
        int yy = rem / 18, xx = rem - yy * 18;
        int gh = h0 + yy - 1, gw = w0 + xx - 1;
        float4 v = make_float4(0.f, 0.f, 0.f, 0.f);
        if ((unsigned)gh < 128u && (unsigned)gw < 128u) {
            const float* srcp = (ci < 16)
                ? (g_psps1 + ((((size_t)n * 16 + ci)        * 128 + gh) * 128 + gw) * TT + t0)
                : (g_psp0  + ((((size_t)n * 2  + (ci - 16)) * 128 + gh) * 128 + gw) * TT + t0);
            v = *(const float4*)srcp;
        }
        *(float4*)&tile[(size_t)i * 4] = v;
    }
    __syncthreads();

    ull acc2[16];                // acc2[c*2 + tpair], c = co within group
#pragma unroll
    for (int i = 0; i < 16; i++) acc2[i] = 0ull;

    for (int ci = 0; ci < 18; ci++) {
#pragma unroll
        for (int ky = 0; ky < 3; ky++)
#pragma unroll
            for (int kx = 0; kx < 3; kx++) {
                ulonglong2 in2 = *(const ulonglong2*)
                    &tile[(((ci * 18) + (y + ky)) * 18 + (x + kx)) * 4];
                const ulonglong2* wrow =
                    (const ulonglong2*)&wP[(ci * 9 + ky * 3 + kx) * 16 + cg * 8];
                ulonglong2 w01 = wrow[0], w23 = wrow[1], w45 = wrow[2], w67 = wrow[3];
                acc2[ 0] = f2fma(in2.x, w01.x, acc2[ 0]);
                acc2[ 1] = f2fma(in2.y, w01.x, acc2[ 1]);
                acc2[ 2] = f2fma(in2.x, w01.y, acc2[ 2]);
                acc2[ 3] = f2fma(in2.y, w01.y, acc2[ 3]);
                acc2[ 4] = f2fma(in2.x, w23.x, acc2[ 4]);
                acc2[ 5] = f2fma(in2.y, w23.x, acc2[ 5]);
                acc2[ 6] = f2fma(in2.x, w23.y, acc2[ 6]);
                acc2[ 7] = f2fma(in2.y, w23.y, acc2[ 7]);
                acc2[ 8] = f2fma(in2.x, w45.x, acc2[ 8]);
                acc2[ 9] = f2fma(in2.y, w45.x, acc2[ 9]);
                acc2[10] = f2fma(in2.x, w45.y, acc2[10]);
                acc2[11] = f2fma(in2.y, w45.y, acc2[11]);
                acc2[12] = f2fma(in2.x, w67.x, acc2[12]);
                acc2[13] = f2fma(in2.y, w67.x, acc2[13]);
                acc2[14] = f2fma(in2.x, w67.y, acc2[14]);
                acc2[15] = f2fma(in2.y, w67.y, acc2[15]);
            }
    }

    int gh = h0 + y, gw = w0 + x;
#pragma unroll
    for (int c = 0; c < 8; c++) {
        int co = cg * 8 + c;
        size_t o = ((((size_t)n * 16 + co) * 128 + gh) * 128 + gw) * TT + t0;
        *(ulonglong2*)&g_p2[o] = make_ulonglong2(acc2[c*2], acc2[c*2 + 1]);
    }
}

// ---------------- fused: spike2 (theta=5) + psp(s2,srm2) + conv3 (1x1) ------
#define SM_STRIDE 36
__global__ void __launch_bounds__(256, 2) k_l3(const float* __restrict__ w3,
                                               float* __restrict__ out) {
    __shared__ float sm_in[18 * 16 * SM_STRIDE];   // [ci][p][t], padded stride
    __shared__ ull   wS[18 * 32];                  // [ci][co] (w,w) pairs

    int tid = threadIdx.x;
    int n = blockIdx.z, h = blockIdx.y, w0 = blockIdx.x * 16;

    for (int i = tid; i < 576; i += 256) {         // w3: [co][ci]
        int co = i & 31, ci = i >> 5;
        float wgt = w3[co * 18 + ci];
        wS[i] = f2pack(wgt, wgt);                  // wS[ci*32+co]
    }

    // ---- phase 1: spike2 + psp(s2) per (pixel, channel), exact replay ----
    {
        int p  = tid & 15;
        int ci = tid >> 4;
        const float4* src = (const float4*)(g_p2 +
            ((((size_t)n * 16 + ci) * 128 + h) * 128 + (w0 + p)) * TT);
        float pv[TT];
#pragma unroll
        for (int v = 0; v < 8; v++) {
            float4 f = src[v];
            pv[4*v] = f.x; pv[4*v+1] = f.y; pv[4*v+2] = f.z; pv[4*v+3] = f.w;
        }
        float rc[32];
#pragma unroll
        for (int d = 1; d < 32; d++) rc[d] = g_refc2[d];
        float r[TT];
#pragma unroll
        for (int t = 0; t < TT; t++) r[t] = 0.f;
        float A = 0.f, B = 0.f;
#pragma unroll
        for (int t = 0; t < TT; t++) {
            float u = pv[t] + r[t];
            bool sp = (u >= 5.0f);
            B = Q2F * (B + A);
            A = Q2F * A + (sp ? 1.0f : 0.0f);
            pv[t] = CS2F * B;                  // psp(s2)
            if (sp) {
#pragma unroll
                for (int d = 1; d < 32; d++)
                    if (t + d < TT) r[t + d] += rc[d];
            }
        }
        float* drow = &sm_in[(ci * 16 + p) * SM_STRIDE];
#pragma unroll
        for (int v = 0; v < 8; v++)
            *(float4*)&drow[4*v] = make_float4(pv[4*v], pv[4*v+1], pv[4*v+2], pv[4*v+3]);

        if (tid < 32) {                        // psp0 channels 16,17
            int pp = tid & 15, c = tid >> 4;
            const float4* s2 = (const float4*)(g_psp0 +
                (((size_t)n * 2 + c) * 16384 + h * 128 + (w0 + pp)) * TT);
            float* dr = &sm_in[((16 + c) * 16 + pp) * SM_STRIDE];
#pragma unroll
            for (int v = 0; v < 8; v++) *(float4*)&dr[4*v] = s2[v];
        }
    }
    __syncthreads();

    // ---- phase 2: 1x1 conv (18 -> 32), f32x2 ----
    int p  = tid >> 4;
    int q  = tid & 15;
    int cohalf = q >> 3;
    int t0 = (q & 7) * 4;

    ull acc2[32];
#pragma unroll
    for (int i = 0; i < 32; i++) acc2[i] = 0ull;

#pragma unroll
    for (int ci = 0; ci < 18; ci++) {
        ulonglong2 in2 = *(const ulonglong2*)&sm_in[(ci * 16 + p) * SM_STRIDE + t0];
#pragma unroll
        for (int cp = 0; cp < 8; cp++) {
            ulonglong2 wv = *(const ulonglong2*)&wS[ci * 32 + cohalf * 16 + cp * 2];
            acc2[cp*4+0] = f2fma(in2.x, wv.x, acc2[cp*4+0]);
            acc2[cp*4+1] = f2fma(in2.y, wv.x, acc2[cp*4+1]);
            acc2[cp*4+2] = f2fma(in2.x, wv.y, acc2[cp*4+2]);
            acc2[cp*4+3] = f2fma(in2.y, wv.y, acc2[cp*4+3]);
        }
    }

    int hw = h * 128 + w0 + p;
#pragma unroll
    for (int cp = 0; cp < 8; cp++) {
#pragma unroll
        for (int s = 0; s < 2; s++) {
            int co = cohalf * 16 + cp * 2 + s;
            size_t o = (((size_t)n * 32 + co) * 16384 + hw) * TT + t0;
            *(ulonglong2*)(out + o) = make_ulonglong2(acc2[cp*4 + 2*s], acc2[cp*4 + 2*s + 1]);
        }
    }
}

// ---------------- launcher ---------------------------------------------------
extern "C" void kernel_launch(void* const* d_in, const int* in_sizes, int n_in,
                              void* d_out, int out_size) {
    const float* spikeIn = (const float*)d_in[0];
    const float* w1 = (const float*)d_in[1];
    const float* w2 = (const float*)d_in[2];
    const float* w3 = (const float*)d_in[3];
    float* out = (float*)d_out;

    const int conv2_smem = 23328 * 4 + 2592 * 8;         // 114,048 B
    cudaFuncSetAttribute(k_conv2, cudaFuncAttributeMaxDynamicSharedMemorySize, conv2_smem);

    k_init<<<1, 32>>>();
    k_psp0<<<512, 256>>>(spikeIn);
    dim3 g1(8, 8, 32);
    k_l1a<<<g1, 512>>>(w1);
    k_l1b<<<4096, 256>>>();
    dim3 g2(8, 8, 32);
    k_conv2<<<g2, 512, conv2_smem>>>(w2);
    dim3 g3(8, 128, 4);
    k_l3<<<g3, 256>>>(w3, out);
}